// round 1
// baseline (speedup 1.0000x reference)
#include <cuda_runtime.h>
#include <cstdint>

// Problem constants (fixed by the dataset)
#define BQ 256      // batch
#define AQ 128      // atoms per molecule
#define FQ 512      // atom features (GEMM K)
#define DQ 6        // max degree
#define CQ 512      // conv width (GEMM N)
#define BA (BQ*AQ)  // 32768 total atoms (GEMM M, split across degree buckets)

// GEMM tiling
#define MT 128
#define NT 128
#define KT 16
#define PAD 132     // padded shared-row stride (floats); 132*4 bytes = 528 = 16*33, keeps float4 alignment

// ---- Scratch (static device globals; no runtime allocation) ----
__device__ float g_summed[(size_t)BA * FQ];   // 64 MB: summed neighbor features per atom
__device__ int   g_lists[DQ][BA];             // per-degree atom-id lists
__device__ int   g_counts[DQ];                // per-degree counts (reset each launch)

// ---------------------------------------------------------------------------
// Kernel 0: reset per-degree counters (must run each launch for graph replay)
// ---------------------------------------------------------------------------
__global__ void reset_counts_kernel() {
    if (threadIdx.x < DQ) g_counts[threadIdx.x] = 0;
}

// ---------------------------------------------------------------------------
// Kernel 1: per-atom neighbor gather + sum, degree bucketing.
// One block per atom, 128 threads, each thread owns 4 contiguous floats (float4).
// summed[atom] = atoms[atom] + sum_{valid bonds} atoms[b, bond]
// ---------------------------------------------------------------------------
__global__ __launch_bounds__(128) void gather_sum_kernel(
    const float* __restrict__ atoms, const int* __restrict__ bonds)
{
    const int atom = blockIdx.x;          // 0 .. BA-1
    const int bimg = atom / AQ;           // molecule index

    // Read this atom's bond slots (6 ints)
    const int* bd = bonds + (size_t)atom * DQ;
    int nb[DQ];
    int deg = 0;
    #pragma unroll
    for (int i = 0; i < DQ; i++) {
        nb[i] = bd[i];
        if (nb[i] >= 0) deg++;
    }
    // deg is in [0, DQ-1] by construction of the dataset; clamp defensively.
    if (deg >= DQ) deg = DQ - 1;

    if (threadIdx.x == 0) {
        int slot = atomicAdd(&g_counts[deg], 1);
        g_lists[deg][slot] = atom;
    }

    const float4* A4 = reinterpret_cast<const float4*>(atoms);
    const int t = threadIdx.x;            // 0..127 -> FQ/4 = 128 float4 per row

    float4 acc = A4[(size_t)atom * (FQ / 4) + t];
    #pragma unroll
    for (int i = 0; i < DQ; i++) {
        if (nb[i] >= 0) {
            float4 v = A4[((size_t)bimg * AQ + nb[i]) * (FQ / 4) + t];
            acc.x += v.x; acc.y += v.y; acc.z += v.z; acc.w += v.w;
        }
    }
    reinterpret_cast<float4*>(g_summed)[(size_t)atom * (FQ / 4) + t] = acc;
}

// ---------------------------------------------------------------------------
// Kernel 2: per-degree gathered GEMM.
//   For degree d: out[list_d[m], :] = summed[list_d[m], :] @ W[d] + b[d]
// 128x128 tile per block, 256 threads, 8x8 register micro-tile, K-step 16.
// grid = (BA/MT, CQ/NT, DQ); blocks past the bucket count exit immediately.
// ---------------------------------------------------------------------------
__global__ __launch_bounds__(256) void gemm_kernel(
    const float* __restrict__ W, const float* __restrict__ bias,
    float* __restrict__ out)
{
    const int d   = blockIdx.z;
    const int cnt = g_counts[d];
    const int m0  = blockIdx.x * MT;
    if (m0 >= cnt) return;
    const int n0  = blockIdx.y * NT;

    __shared__ float As[KT][PAD];   // As[k][m]
    __shared__ float Bs[KT][PAD];   // Bs[k][n]
    __shared__ int   rows[MT];

    const int t = threadIdx.x;      // 0..255
    if (t < MT) {
        int m = m0 + t;
        rows[t] = (m < cnt) ? g_lists[d][m] : -1;
    }
    __syncthreads();

    const int tx = t & 15;          // N direction (8 cols each)
    const int ty = t >> 4;          // M direction (8 rows each)

    float acc[8][8];
    #pragma unroll
    for (int i = 0; i < 8; i++)
        #pragma unroll
        for (int j = 0; j < 8; j++) acc[i][j] = 0.0f;

    const float* Wd = W + (size_t)d * FQ * CQ;

    for (int k0 = 0; k0 < FQ; k0 += KT) {
        // --- Load A tile: As[k][m] = summed[rows[m]][k0+k].
        // 512 float4 slots (128 rows x 4 float4-of-k). 2 per thread.
        #pragma unroll
        for (int j = 0; j < 2; j++) {
            int s  = t + j * 256;
            int m  = s >> 2;        // row within tile
            int kk = s & 3;         // which float4 along k
            int row = rows[m];
            float4 v = make_float4(0.f, 0.f, 0.f, 0.f);
            if (row >= 0)
                v = *reinterpret_cast<const float4*>(
                        g_summed + (size_t)row * FQ + k0 + kk * 4);
            As[kk * 4 + 0][m] = v.x;
            As[kk * 4 + 1][m] = v.y;
            As[kk * 4 + 2][m] = v.z;
            As[kk * 4 + 3][m] = v.w;
        }
        // --- Load B tile: Bs[k][n] = Wd[(k0+k)*CQ + n0+n]. Fully coalesced.
        #pragma unroll
        for (int j = 0; j < 2; j++) {
            int s  = t + j * 256;
            int k  = s >> 5;        // 32 float4 per k-row
            int nn = s & 31;
            float4 v = *reinterpret_cast<const float4*>(
                           Wd + (size_t)(k0 + k) * CQ + n0 + nn * 4);
            *reinterpret_cast<float4*>(&Bs[k][nn * 4]) = v;
        }
        __syncthreads();

        #pragma unroll
        for (int k = 0; k < KT; k++) {
            float af[8], bf[8];
            #pragma unroll
            for (int i = 0; i < 8; i++) af[i] = As[k][ty * 8 + i];
            #pragma unroll
            for (int i = 0; i < 8; i++) bf[i] = Bs[k][tx * 8 + i];
            #pragma unroll
            for (int i = 0; i < 8; i++)
                #pragma unroll
                for (int j = 0; j < 8; j++)
                    acc[i][j] += af[i] * bf[j];
        }
        __syncthreads();
    }

    // --- Epilogue: scatter rows back to their atom ids, add bias.
    #pragma unroll
    for (int i = 0; i < 8; i++) {
        int m   = ty * 8 + i;
        int row = rows[m];
        if (row < 0) continue;
        float* op = out + (size_t)row * CQ + n0 + tx * 8;
        const float* bp = bias + (size_t)d * CQ + n0 + tx * 8;
        #pragma unroll
        for (int j = 0; j < 8; j++)
            op[j] = acc[i][j] + bp[j];
    }
}

// ---------------------------------------------------------------------------
// Launch
// ---------------------------------------------------------------------------
extern "C" void kernel_launch(void* const* d_in, const int* in_sizes, int n_in,
                              void* d_out, int out_size)
{
    const float* atoms = (const float*)d_in[0];   // [B, A, F] fp32
    const int*   bonds = (const int*)  d_in[1];   // [B, A, D] int32
    const float* W     = (const float*)d_in[2];   // [D, F, C] fp32
    const float* bias  = (const float*)d_in[3];   // [D, C]    fp32
    float*       out   = (float*)d_out;           // [B, A, C] fp32

    reset_counts_kernel<<<1, 32>>>();
    gather_sum_kernel<<<BA, 128>>>(atoms, bonds);

    dim3 grid(BA / MT, CQ / NT, DQ);
    gemm_kernel<<<grid, 256>>>(W, bias, out);
}

// round 2
// speedup vs baseline: 1.0025x; 1.0025x over previous
#include <cuda_runtime.h>
#include <cstdint>

// Problem constants (fixed by the dataset)
#define BQ 256      // batch
#define AQ 128      // atoms per molecule
#define FQ 512      // atom features (GEMM K)
#define DQ 6        // max degree
#define CQ 512      // conv width (GEMM N)
#define BA (BQ*AQ)  // 32768 total atoms (GEMM M, split across degree buckets)

// GEMM tiling
#define MT 128
#define NT 128
#define KT 16
#define PAD 132     // padded shared-row stride (floats); 132*4 bytes = 528 = 16*33, keeps float4 alignment

// ---- Scratch (static device globals; no runtime allocation) ----
__device__ float g_summed[(size_t)BA * FQ];   // 64 MB: summed neighbor features per atom
__device__ int   g_lists[DQ][BA];             // per-degree atom-id lists
__device__ int   g_counts[DQ];                // per-degree counts (reset each launch)

// ---------------------------------------------------------------------------
// Kernel 0: reset per-degree counters (must run each launch for graph replay)
// ---------------------------------------------------------------------------
__global__ void reset_counts_kernel() {
    if (threadIdx.x < DQ) g_counts[threadIdx.x] = 0;
}

// ---------------------------------------------------------------------------
// Kernel 1: per-atom neighbor gather + sum, degree bucketing.
// One block per atom, 128 threads, each thread owns 4 contiguous floats (float4).
// summed[atom] = atoms[atom] + sum_{valid bonds} atoms[b, bond]
// ---------------------------------------------------------------------------
__global__ __launch_bounds__(128) void gather_sum_kernel(
    const float* __restrict__ atoms, const int* __restrict__ bonds)
{
    const int atom = blockIdx.x;          // 0 .. BA-1
    const int bimg = atom / AQ;           // molecule index

    // Read this atom's bond slots (6 ints)
    const int* bd = bonds + (size_t)atom * DQ;
    int nb[DQ];
    int deg = 0;
    #pragma unroll
    for (int i = 0; i < DQ; i++) {
        nb[i] = bd[i];
        if (nb[i] >= 0) deg++;
    }
    // deg is in [0, DQ-1] by construction of the dataset; clamp defensively.
    if (deg >= DQ) deg = DQ - 1;

    if (threadIdx.x == 0) {
        int slot = atomicAdd(&g_counts[deg], 1);
        g_lists[deg][slot] = atom;
    }

    const float4* A4 = reinterpret_cast<const float4*>(atoms);
    const int t = threadIdx.x;            // 0..127 -> FQ/4 = 128 float4 per row

    float4 acc = A4[(size_t)atom * (FQ / 4) + t];
    #pragma unroll
    for (int i = 0; i < DQ; i++) {
        if (nb[i] >= 0) {
            float4 v = A4[((size_t)bimg * AQ + nb[i]) * (FQ / 4) + t];
            acc.x += v.x; acc.y += v.y; acc.z += v.z; acc.w += v.w;
        }
    }
    reinterpret_cast<float4*>(g_summed)[(size_t)atom * (FQ / 4) + t] = acc;
}

// ---------------------------------------------------------------------------
// Kernel 2: per-degree gathered GEMM.
//   For degree d: out[list_d[m], :] = summed[list_d[m], :] @ W[d] + b[d]
// 128x128 tile per block, 256 threads, 8x8 register micro-tile, K-step 16.
// grid = (BA/MT, CQ/NT, DQ); blocks past the bucket count exit immediately.
// ---------------------------------------------------------------------------
__global__ __launch_bounds__(256) void gemm_kernel(
    const float* __restrict__ W, const float* __restrict__ bias,
    float* __restrict__ out)
{
    const int d   = blockIdx.z;
    const int cnt = g_counts[d];
    const int m0  = blockIdx.x * MT;
    if (m0 >= cnt) return;
    const int n0  = blockIdx.y * NT;

    __shared__ float As[KT][PAD];   // As[k][m]
    __shared__ float Bs[KT][PAD];   // Bs[k][n]
    __shared__ int   rows[MT];

    const int t = threadIdx.x;      // 0..255
    if (t < MT) {
        int m = m0 + t;
        rows[t] = (m < cnt) ? g_lists[d][m] : -1;
    }
    __syncthreads();

    const int tx = t & 15;          // N direction (8 cols each)
    const int ty = t >> 4;          // M direction (8 rows each)

    float acc[8][8];
    #pragma unroll
    for (int i = 0; i < 8; i++)
        #pragma unroll
        for (int j = 0; j < 8; j++) acc[i][j] = 0.0f;

    const float* Wd = W + (size_t)d * FQ * CQ;

    for (int k0 = 0; k0 < FQ; k0 += KT) {
        // --- Load A tile: As[k][m] = summed[rows[m]][k0+k].
        // 512 float4 slots (128 rows x 4 float4-of-k). 2 per thread.
        #pragma unroll
        for (int j = 0; j < 2; j++) {
            int s  = t + j * 256;
            int m  = s >> 2;        // row within tile
            int kk = s & 3;         // which float4 along k
            int row = rows[m];
            float4 v = make_float4(0.f, 0.f, 0.f, 0.f);
            if (row >= 0)
                v = *reinterpret_cast<const float4*>(
                        g_summed + (size_t)row * FQ + k0 + kk * 4);
            As[kk * 4 + 0][m] = v.x;
            As[kk * 4 + 1][m] = v.y;
            As[kk * 4 + 2][m] = v.z;
            As[kk * 4 + 3][m] = v.w;
        }
        // --- Load B tile: Bs[k][n] = Wd[(k0+k)*CQ + n0+n]. Fully coalesced.
        #pragma unroll
        for (int j = 0; j < 2; j++) {
            int s  = t + j * 256;
            int k  = s >> 5;        // 32 float4 per k-row
            int nn = s & 31;
            float4 v = *reinterpret_cast<const float4*>(
                           Wd + (size_t)(k0 + k) * CQ + n0 + nn * 4);
            *reinterpret_cast<float4*>(&Bs[k][nn * 4]) = v;
        }
        __syncthreads();

        #pragma unroll
        for (int k = 0; k < KT; k++) {
            float af[8], bf[8];
            #pragma unroll
            for (int i = 0; i < 8; i++) af[i] = As[k][ty * 8 + i];
            #pragma unroll
            for (int i = 0; i < 8; i++) bf[i] = Bs[k][tx * 8 + i];
            #pragma unroll
            for (int i = 0; i < 8; i++)
                #pragma unroll
                for (int j = 0; j < 8; j++)
                    acc[i][j] += af[i] * bf[j];
        }
        __syncthreads();
    }

    // --- Epilogue: scatter rows back to their atom ids, add bias.
    #pragma unroll
    for (int i = 0; i < 8; i++) {
        int m   = ty * 8 + i;
        int row = rows[m];
        if (row < 0) continue;
        float* op = out + (size_t)row * CQ + n0 + tx * 8;
        const float* bp = bias + (size_t)d * CQ + n0 + tx * 8;
        #pragma unroll
        for (int j = 0; j < 8; j++)
            op[j] = acc[i][j] + bp[j];
    }
}

// ---------------------------------------------------------------------------
// Launch
// ---------------------------------------------------------------------------
extern "C" void kernel_launch(void* const* d_in, const int* in_sizes, int n_in,
                              void* d_out, int out_size)
{
    const float* atoms = (const float*)d_in[0];   // [B, A, F] fp32
    const int*   bonds = (const int*)  d_in[1];   // [B, A, D] int32
    const float* W     = (const float*)d_in[2];   // [D, F, C] fp32
    const float* bias  = (const float*)d_in[3];   // [D, C]    fp32
    float*       out   = (float*)d_out;           // [B, A, C] fp32

    reset_counts_kernel<<<1, 32>>>();
    gather_sum_kernel<<<BA, 128>>>(atoms, bonds);

    dim3 grid(BA / MT, CQ / NT, DQ);
    gemm_kernel<<<grid, 256>>>(W, bias, out);
}

// round 4
// speedup vs baseline: 2.6784x; 2.6716x over previous
#include <cuda_runtime.h>
#include <cuda_bf16.h>
#include <cstdint>

// ---------------- Problem constants ----------------
#define BQ 256
#define AQ 128
#define FQ 512      // GEMM K
#define DQ 6
#define CQ 512      // GEMM N total
#define BA (BQ*AQ)               // 32768 atoms
#define ROWS_PAD (BA + DQ*128)   // compacted rows incl. per-bucket 128-alignment padding

// ---------------- GEMM tiling ----------------
#define MT 128
#define NT 128
#define KC 64                  // k-tile: 64 bf16 = 128B rows (8x16B chunks, XOR-swizzled)
#define NK (FQ/KC)             // 8
#define TILE_B 16384           // 128 rows * 128 B
#define OFF_AH 0
#define OFF_AL 16384
#define OFF_BH 32768
#define OFF_BL 49152
#define STAGE_B 65536
#define DYN_SMEM (2*STAGE_B + 1024)

// ---------------- Static scratch (no runtime allocation) ----------------
__device__ __nv_bfloat16 g_Ahi[(size_t)ROWS_PAD * FQ];
__device__ __nv_bfloat16 g_Alo[(size_t)ROWS_PAD * FQ];
__device__ __nv_bfloat16 g_Whi[(size_t)DQ * CQ * FQ];   // [d][n][k] (transposed)
__device__ __nv_bfloat16 g_Wlo[(size_t)DQ * CQ * FQ];
__device__ int g_rowatom[ROWS_PAD];
__device__ int g_slotpack[BA];
__device__ int g_counts[DQ];
__device__ int g_base[DQ];

// ---------------- helpers ----------------
static __device__ __forceinline__ uint32_t smem_u32(const void* p) {
    uint32_t a;
    asm("{ .reg .u64 t; cvta.to.shared.u64 t, %1; cvt.u32.u64 %0, t; }"
        : "=r"(a) : "l"(p));
    return a;
}
static __device__ __forceinline__ void cp16(uint32_t dst, const void* src) {
    asm volatile("cp.async.cg.shared.global [%0], [%1], 16;"
                 :: "r"(dst), "l"(src) : "memory");
}
#define LDSM_X4(r, addr) \
    asm volatile("ldmatrix.sync.aligned.m8n8.x4.shared.b16 {%0,%1,%2,%3}, [%4];" \
                 : "=r"((r)[0]), "=r"((r)[1]), "=r"((r)[2]), "=r"((r)[3]) \
                 : "r"(addr))
static __device__ __forceinline__ void mma_bf16(float* c, const uint32_t* a,
                                                const uint32_t* b) {
    asm volatile(
        "mma.sync.aligned.m16n8k16.row.col.f32.bf16.bf16.f32 "
        "{%0,%1,%2,%3}, {%4,%5,%6,%7}, {%8,%9}, {%0,%1,%2,%3};"
        : "+f"(c[0]), "+f"(c[1]), "+f"(c[2]), "+f"(c[3])
        : "r"(a[0]), "r"(a[1]), "r"(a[2]), "r"(a[3]), "r"(b[0]), "r"(b[1]));
}
// SW128-style XOR swizzle, specialized: offset(row, chunk j) within a 128x128B tile
static __device__ __forceinline__ uint32_t swz(int row, int j) {
    return (uint32_t)(row * 128 + ((j ^ (row & 7)) * 16));
}

// ---------------------------------------------------------------------------
// Kernel 0: zero bucket counters (graph-replay idempotence).
// ---------------------------------------------------------------------------
__global__ void reset_counts_kernel() {
    if (threadIdx.x < DQ) g_counts[threadIdx.x] = 0;
}

// ---------------------------------------------------------------------------
// Kernel 1: per-atom degree + bucket slot; fill g_rowatom with -1.
// ---------------------------------------------------------------------------
__global__ __launch_bounds__(256) void bucket_kernel(const int* __restrict__ bonds) {
    int i = blockIdx.x * blockDim.x + threadIdx.x;
    for (int j = i; j < ROWS_PAD; j += gridDim.x * blockDim.x) g_rowatom[j] = -1;
    if (i < BA) {
        const int* bd = bonds + (size_t)i * DQ;
        int deg = 0;
        #pragma unroll
        for (int k = 0; k < DQ; k++) deg += (bd[k] >= 0);
        if (deg > DQ - 1) deg = DQ - 1;
        int slot = atomicAdd(&g_counts[deg], 1);
        g_slotpack[i] = (deg << 16) | slot;
    }
}

// ---------------------------------------------------------------------------
// Kernel 2: 128-aligned exclusive scan of bucket counts (tiny).
// ---------------------------------------------------------------------------
__global__ void scan_kernel() {
    if (threadIdx.x == 0) {
        int b = 0;
        #pragma unroll
        for (int d = 0; d < DQ; d++) {
            g_base[d] = b;
            b += ((g_counts[d] + 127) >> 7) << 7;
        }
    }
}

// ---------------------------------------------------------------------------
// Kernel 3: gather+sum per atom, split fp32 -> bf16 hi/lo, write at compacted
// bucket position. One block per atom, 128 threads (float4 each).
// ---------------------------------------------------------------------------
__global__ __launch_bounds__(128) void gather_split_kernel(
    const float* __restrict__ atoms, const int* __restrict__ bonds)
{
    const int atom = blockIdx.x;
    const int bimg = atom >> 7;
    const int* bd = bonds + (size_t)atom * DQ;
    int nb[DQ];
    #pragma unroll
    for (int i = 0; i < DQ; i++) nb[i] = bd[i];

    const int pack = g_slotpack[atom];
    const int deg = pack >> 16, slot = pack & 0xFFFF;
    const int pos = g_base[deg] + slot;

    const float4* A4 = reinterpret_cast<const float4*>(atoms);
    const int t = threadIdx.x;

    float4 acc = A4[(size_t)atom * (FQ / 4) + t];
    #pragma unroll
    for (int i = 0; i < DQ; i++) {
        if (nb[i] >= 0) {
            float4 v = A4[((size_t)(bimg * AQ + nb[i])) * (FQ / 4) + t];
            acc.x += v.x; acc.y += v.y; acc.z += v.z; acc.w += v.w;
        }
    }

    float vv[4] = {acc.x, acc.y, acc.z, acc.w};
    __nv_bfloat16 h[4], l[4];
    #pragma unroll
    for (int e = 0; e < 4; e++) {
        h[e] = __float2bfloat16_rn(vv[e]);
        l[e] = __float2bfloat16_rn(vv[e] - __bfloat162float(h[e]));
    }
    size_t o = (size_t)pos * FQ + t * 4;
    __nv_bfloat162 h01; h01.x = h[0]; h01.y = h[1];
    __nv_bfloat162 h23; h23.x = h[2]; h23.y = h[3];
    __nv_bfloat162 l01; l01.x = l[0]; l01.y = l[1];
    __nv_bfloat162 l23; l23.x = l[2]; l23.y = l[3];
    reinterpret_cast<__nv_bfloat162*>(g_Ahi + o)[0] = h01;
    reinterpret_cast<__nv_bfloat162*>(g_Ahi + o)[1] = h23;
    reinterpret_cast<__nv_bfloat162*>(g_Alo + o)[0] = l01;
    reinterpret_cast<__nv_bfloat162*>(g_Alo + o)[1] = l23;
    if (t == 0) g_rowatom[pos] = atom;
}

// ---------------------------------------------------------------------------
// Kernel 4: transpose W [d][k][n] -> [d][n][k], split to bf16 hi/lo.
// ---------------------------------------------------------------------------
__global__ __launch_bounds__(256) void wsplit_kernel(const float* __restrict__ W) {
    __shared__ float tile[32][33];
    const int d = blockIdx.z;
    const int kb = blockIdx.x * 32, nb = blockIdx.y * 32;
    const int tx = threadIdx.x, ty = threadIdx.y;  // 32 x 8
    #pragma unroll
    for (int i = 0; i < 4; i++)
        tile[ty + 8 * i][tx] = W[((size_t)d * FQ + kb + ty + 8 * i) * CQ + nb + tx];
    __syncthreads();
    #pragma unroll
    for (int i = 0; i < 4; i++) {
        float v = tile[tx][ty + 8 * i];
        __nv_bfloat16 h = __float2bfloat16_rn(v);
        __nv_bfloat16 lo = __float2bfloat16_rn(v - __bfloat162float(h));
        size_t o = ((size_t)d * CQ + nb + ty + 8 * i) * FQ + kb + tx;
        g_Whi[o] = h;
        g_Wlo[o] = lo;
    }
}

// ---------------------------------------------------------------------------
// Kernel 5: bf16 split GEMM via mma.sync.m16n8k16 (HMMA).
// CTA 128x128, 8 warps (2x4), warp tile 64x32; BK=64, 2-stage cp.async.
// acc(fp32) += Ahi*Bhi + Ahi*Blo + Alo*Bhi
// ---------------------------------------------------------------------------
static __device__ __forceinline__ void load_stage(uint32_t sb, int cbase, int wrow,
                                                  int k0, int tid) {
    #pragma unroll
    for (int i = 0; i < 4; i++) {
        int c = i * 256 + tid;          // 1024 16B-chunks per 16KB tile
        int r = c >> 3, j = c & 7;
        uint32_t off = swz(r, j);
        size_t goA = (size_t)(cbase + r) * FQ + k0 + j * 8;
        cp16(sb + OFF_AH + off, g_Ahi + goA);
        cp16(sb + OFF_AL + off, g_Alo + goA);
        size_t goB = (size_t)(wrow + r) * FQ + k0 + j * 8;
        cp16(sb + OFF_BH + off, g_Whi + goB);
        cp16(sb + OFF_BL + off, g_Wlo + goB);
    }
    asm volatile("cp.async.commit_group;" ::: "memory");
}

__global__ __launch_bounds__(256, 1) void gemm_mma_kernel(
    const float* __restrict__ bias, float* __restrict__ out)
{
    const int d = blockIdx.z;
    const int cnt = g_counts[d];
    if ((int)blockIdx.x * MT >= cnt) return;
    const int n0 = blockIdx.y * NT;
    const int cbase = g_base[d] + blockIdx.x * MT;
    const int wrow = d * CQ + n0;

    extern __shared__ char dsm[];
    const uint32_t sb = (smem_u32(dsm) + 1023u) & ~1023u;
    const int tid = threadIdx.x, wid = tid >> 5, lane = tid & 31;
    const int wm = (wid & 1) * 64;       // warp M offset in tile
    const int wn = (wid >> 1) * 32;      // warp N offset in tile

    float acc[4][4][4];
    #pragma unroll
    for (int i = 0; i < 4; i++)
        #pragma unroll
        for (int j = 0; j < 4; j++)
            #pragma unroll
            for (int q = 0; q < 4; q++) acc[i][j][q] = 0.f;

    // lane-derived fragment addressing pieces
    const int a_row = wm + (lane & 15);          // + i*16
    const int a_jlo = lane >> 4;                 // chunk-half bit
    const int b_mi  = lane >> 3;                 // 0..3 (x4 matrix index)
    const int b_rb  = wn + ((b_mi >> 1) * 8) + (lane & 7);  // + jj*16
    const int b_jlo = b_mi & 1;

    load_stage(sb, cbase, wrow, 0, tid);
    load_stage(sb + STAGE_B, cbase, wrow, KC, tid);

    #pragma unroll 1
    for (int c = 0; c < NK; c++) {
        const uint32_t st = sb + (c & 1) * STAGE_B;
        if (c < NK - 1) asm volatile("cp.async.wait_group 1;" ::: "memory");
        else            asm volatile("cp.async.wait_group 0;" ::: "memory");
        __syncthreads();

        #pragma unroll
        for (int s = 0; s < 4; s++) {               // 4 x k16 per k-tile
            uint32_t ah[4][4], al[4][4], bh[4][2], bl[4][2];
            #pragma unroll
            for (int i = 0; i < 4; i++) {           // A frags (hi+lo)
                int row = a_row + i * 16;
                uint32_t off = swz(row, s * 2 + a_jlo);
                LDSM_X4(ah[i], st + OFF_AH + off);
                LDSM_X4(al[i], st + OFF_AL + off);
            }
            #pragma unroll
            for (int jj = 0; jj < 2; jj++) {        // B frags (hi+lo), 2 ntiles per x4
                int row = b_rb + jj * 16;
                uint32_t off = swz(row, s * 2 + b_jlo);
                uint32_t r4[4];
                LDSM_X4(r4, st + OFF_BH + off);
                bh[jj*2][0] = r4[0]; bh[jj*2][1] = r4[1];
                bh[jj*2+1][0] = r4[2]; bh[jj*2+1][1] = r4[3];
                LDSM_X4(r4, st + OFF_BL + off);
                bl[jj*2][0] = r4[0]; bl[jj*2][1] = r4[1];
                bl[jj*2+1][0] = r4[2]; bl[jj*2+1][1] = r4[3];
            }
            #pragma unroll
            for (int i = 0; i < 4; i++)
                #pragma unroll
                for (int j = 0; j < 4; j++) {
                    mma_bf16(acc[i][j], ah[i], bh[j]);
                    mma_bf16(acc[i][j], ah[i], bl[j]);
                    mma_bf16(acc[i][j], al[i], bh[j]);
                }
        }
        __syncthreads();
        if (c + 2 < NK)
            load_stage(sb + (c & 1) * STAGE_B, cbase, wrow, (c + 2) * KC, tid);
    }

    // ---- Epilogue: acc regs -> out rows (scatter by atom id), add bias. ----
    const int g  = lane >> 2;          // row group within m16n8
    const int t4 = lane & 3;           // col pair
    float2 bb[4];
    #pragma unroll
    for (int j = 0; j < 4; j++)
        bb[j] = *reinterpret_cast<const float2*>(
                    bias + d * CQ + n0 + wn + j * 8 + t4 * 2);

    #pragma unroll
    for (int i = 0; i < 4; i++) {
        const int r0 = cbase + wm + i * 16 + g;
        const int a0 = g_rowatom[r0];
        const int a1 = g_rowatom[r0 + 8];
        #pragma unroll
        for (int j = 0; j < 4; j++) {
            const int col = n0 + wn + j * 8 + t4 * 2;
            if (a0 >= 0) {
                float2 v = make_float2(acc[i][j][0] + bb[j].x, acc[i][j][1] + bb[j].y);
                *reinterpret_cast<float2*>(out + (size_t)a0 * CQ + col) = v;
            }
            if (a1 >= 0) {
                float2 v = make_float2(acc[i][j][2] + bb[j].x, acc[i][j][3] + bb[j].y);
                *reinterpret_cast<float2*>(out + (size_t)a1 * CQ + col) = v;
            }
        }
    }
}

// ---------------------------------------------------------------------------
// Launch
// ---------------------------------------------------------------------------
extern "C" void kernel_launch(void* const* d_in, const int* in_sizes, int n_in,
                              void* d_out, int out_size)
{
    const float* atoms = (const float*)d_in[0];   // [B, A, F] fp32
    const int*   bonds = (const int*)  d_in[1];   // [B, A, D] int32
    const float* W     = (const float*)d_in[2];   // [D, F, C] fp32
    const float* bias  = (const float*)d_in[3];   // [D, C]    fp32
    float*       out   = (float*)d_out;           // [B, A, C] fp32

    cudaFuncSetAttribute(gemm_mma_kernel,
                         cudaFuncAttributeMaxDynamicSharedMemorySize, DYN_SMEM);

    reset_counts_kernel<<<1, 32>>>();
    bucket_kernel<<<BA / 256, 256>>>(bonds);
    scan_kernel<<<1, 32>>>();
    gather_split_kernel<<<BA, 128>>>(atoms, bonds);
    wsplit_kernel<<<dim3(FQ / 32, CQ / 32, DQ), dim3(32, 8)>>>(W);
    gemm_mma_kernel<<<dim3(BA / MT, CQ / NT, DQ), 256, DYN_SMEM>>>(bias, out);
}

// round 5
// speedup vs baseline: 5.3296x; 1.9899x over previous
#include <cuda_runtime.h>
#include <cuda_fp16.h>
#include <cstdint>

// ---------------- Problem constants ----------------
#define BQ 256
#define AQ 128
#define FQ 512      // GEMM K
#define DQ 6
#define CQ 512      // GEMM N total
#define BA (BQ*AQ)               // 32768 atoms
#define ROWS_PAD (BA + DQ*128)   // compacted rows incl. per-bucket 128-alignment padding

// ---------------- GEMM tiling ----------------
#define MT 128
#define NT 128
#define KC 64                  // k-tile: 64 fp16 = 128B rows (8x16B chunks, XOR-swizzled)
#define NK (FQ/KC)             // 8
#define OFF_A 0
#define OFF_B 16384
#define STAGE_B 32768
#define DYN_SMEM (2*STAGE_B + 1024)

// ---------------- Static scratch (no runtime allocation) ----------------
__device__ __half g_Ah[(size_t)ROWS_PAD * FQ];        // summed atom features, fp16
__device__ __half g_Wh[(size_t)DQ * CQ * FQ];         // weights [d][n][k] transposed, fp16
__device__ int g_rowatom[ROWS_PAD];
__device__ int g_slotpack[BA];
__device__ int g_counts[DQ];
__device__ int g_base[DQ];
__device__ int g_ticket;                              // self-resetting block ticket

// ---------------- helpers ----------------
static __device__ __forceinline__ uint32_t smem_u32(const void* p) {
    uint32_t a;
    asm("{ .reg .u64 t; cvta.to.shared.u64 t, %1; cvt.u32.u64 %0, t; }"
        : "=r"(a) : "l"(p));
    return a;
}
static __device__ __forceinline__ void cp16(uint32_t dst, const void* src) {
    asm volatile("cp.async.cg.shared.global [%0], [%1], 16;"
                 :: "r"(dst), "l"(src) : "memory");
}
#define LDSM_X4(r, addr) \
    asm volatile("ldmatrix.sync.aligned.m8n8.x4.shared.b16 {%0,%1,%2,%3}, [%4];" \
                 : "=r"((r)[0]), "=r"((r)[1]), "=r"((r)[2]), "=r"((r)[3]) \
                 : "r"(addr))
static __device__ __forceinline__ void mma_fp16(float* c, const uint32_t* a,
                                                const uint32_t* b) {
    asm volatile(
        "mma.sync.aligned.m16n8k16.row.col.f32.f16.f16.f32 "
        "{%0,%1,%2,%3}, {%4,%5,%6,%7}, {%8,%9}, {%0,%1,%2,%3};"
        : "+f"(c[0]), "+f"(c[1]), "+f"(c[2]), "+f"(c[3])
        : "r"(a[0]), "r"(a[1]), "r"(a[2]), "r"(a[3]), "r"(b[0]), "r"(b[1]));
}
// SW128-style XOR swizzle: offset(row, 16B-chunk j) within a 128-row x 128B tile
static __device__ __forceinline__ uint32_t swz(int row, int j) {
    return (uint32_t)(row * 128 + ((j ^ (row & 7)) * 16));
}

// ---------------------------------------------------------------------------
// Kernel A: transpose W [d][k][n] -> [d][n][k] into fp16. Block (0,0,0) also
// resets the bucket counters (this kernel is stream-ordered before bucketing).
// ---------------------------------------------------------------------------
__global__ __launch_bounds__(256) void wsplit_kernel(const float* __restrict__ W) {
    if (blockIdx.x == 0 && blockIdx.y == 0 && blockIdx.z == 0 &&
        threadIdx.y == 0 && threadIdx.x < DQ)
        g_counts[threadIdx.x] = 0;

    __shared__ float tile[32][33];
    const int d = blockIdx.z;
    const int kb = blockIdx.x * 32, nb = blockIdx.y * 32;
    const int tx = threadIdx.x, ty = threadIdx.y;  // 32 x 8
    #pragma unroll
    for (int i = 0; i < 4; i++)
        tile[ty + 8 * i][tx] = W[((size_t)d * FQ + kb + ty + 8 * i) * CQ + nb + tx];
    __syncthreads();
    #pragma unroll
    for (int i = 0; i < 4; i++) {
        float v = tile[tx][ty + 8 * i];
        g_Wh[((size_t)d * CQ + nb + ty + 8 * i) * FQ + kb + tx] = __float2half_rn(v);
    }
}

// ---------------------------------------------------------------------------
// Kernel B: per-atom degree + bucket slot; fill g_rowatom with -1.
// The LAST block to finish computes the 128-aligned exclusive scan of the
// bucket counts (ticket self-resets so graph replays stay idempotent).
// ---------------------------------------------------------------------------
__global__ __launch_bounds__(256) void bucket_kernel(const int* __restrict__ bonds) {
    int i = blockIdx.x * blockDim.x + threadIdx.x;
    for (int j = i; j < ROWS_PAD; j += gridDim.x * blockDim.x) g_rowatom[j] = -1;
    if (i < BA) {
        const int* bd = bonds + (size_t)i * DQ;
        int deg = 0;
        #pragma unroll
        for (int k = 0; k < DQ; k++) deg += (bd[k] >= 0);
        if (deg > DQ - 1) deg = DQ - 1;
        int slot = atomicAdd(&g_counts[deg], 1);
        g_slotpack[i] = (deg << 16) | slot;
    }
    __syncthreads();
    if (threadIdx.x == 0) {
        __threadfence();
        int t = atomicAdd(&g_ticket, 1);
        if (t == (int)gridDim.x - 1) {
            int b = 0;
            #pragma unroll
            for (int d = 0; d < DQ; d++) {
                g_base[d] = b;
                b += ((g_counts[d] + 127) >> 7) << 7;
            }
            g_ticket = 0;      // reset for next replay
            __threadfence();
        }
    }
}

// ---------------------------------------------------------------------------
// Kernel C: gather+sum per atom -> fp16, written at compacted bucket position.
// One block per atom, 128 threads (one float4 of F each).
// ---------------------------------------------------------------------------
__global__ __launch_bounds__(128) void gather_kernel(
    const float* __restrict__ atoms, const int* __restrict__ bonds)
{
    const int atom = blockIdx.x;
    const int bimg = atom >> 7;
    const int* bd = bonds + (size_t)atom * DQ;
    int nb[DQ];
    #pragma unroll
    for (int i = 0; i < DQ; i++) nb[i] = bd[i];

    const int pack = g_slotpack[atom];
    const int pos = g_base[pack >> 16] + (pack & 0xFFFF);

    const float4* A4 = reinterpret_cast<const float4*>(atoms);
    const int t = threadIdx.x;

    float4 acc = A4[(size_t)atom * (FQ / 4) + t];
    #pragma unroll
    for (int i = 0; i < DQ; i++) {
        if (nb[i] >= 0) {
            float4 v = A4[((size_t)(bimg * AQ + nb[i])) * (FQ / 4) + t];
            acc.x += v.x; acc.y += v.y; acc.z += v.z; acc.w += v.w;
        }
    }

    __half2 h01 = __floats2half2_rn(acc.x, acc.y);
    __half2 h23 = __floats2half2_rn(acc.z, acc.w);
    size_t o = (size_t)pos * FQ + t * 4;
    reinterpret_cast<__half2*>(g_Ah + o)[0] = h01;
    reinterpret_cast<__half2*>(g_Ah + o)[1] = h23;
    if (t == 0) g_rowatom[pos] = atom;
}

// ---------------------------------------------------------------------------
// Kernel D: fp16 GEMM via mma.sync.m16n8k16 (HMMA), fp32 accumulate.
// CTA 128x128, 8 warps (2x4), warp tile 64x32; BK=64, 2-stage cp.async.
// ---------------------------------------------------------------------------
static __device__ __forceinline__ void load_stage(uint32_t sb, int cbase, int wrow,
                                                  int k0, int tid) {
    #pragma unroll
    for (int i = 0; i < 4; i++) {
        int c = i * 256 + tid;          // 1024 16B-chunks per 16KB tile
        int r = c >> 3, j = c & 7;
        uint32_t off = swz(r, j);
        cp16(sb + OFF_A + off, g_Ah + (size_t)(cbase + r) * FQ + k0 + j * 8);
        cp16(sb + OFF_B + off, g_Wh + (size_t)(wrow + r) * FQ + k0 + j * 8);
    }
    asm volatile("cp.async.commit_group;" ::: "memory");
}

__global__ __launch_bounds__(256, 2) void gemm_mma_kernel(
    const float* __restrict__ bias, float* __restrict__ out)
{
    const int d = blockIdx.z;
    const int cnt = g_counts[d];
    if ((int)blockIdx.x * MT >= cnt) return;
    const int n0 = blockIdx.y * NT;
    const int cbase = g_base[d] + blockIdx.x * MT;
    const int wrow = d * CQ + n0;

    extern __shared__ char dsm[];
    const uint32_t sb = (smem_u32(dsm) + 1023u) & ~1023u;
    const int tid = threadIdx.x, wid = tid >> 5, lane = tid & 31;
    const int wm = (wid & 1) * 64;       // warp M offset in tile
    const int wn = (wid >> 1) * 32;      // warp N offset in tile

    float acc[4][4][4];
    #pragma unroll
    for (int i = 0; i < 4; i++)
        #pragma unroll
        for (int j = 0; j < 4; j++)
            #pragma unroll
            for (int q = 0; q < 4; q++) acc[i][j][q] = 0.f;

    const int a_row = wm + (lane & 15);
    const int a_jlo = lane >> 4;
    const int b_mi  = lane >> 3;
    const int b_rb  = wn + ((b_mi >> 1) * 8) + (lane & 7);
    const int b_jlo = b_mi & 1;

    load_stage(sb, cbase, wrow, 0, tid);
    load_stage(sb + STAGE_B, cbase, wrow, KC, tid);

    #pragma unroll 1
    for (int c = 0; c < NK; c++) {
        const uint32_t st = sb + (c & 1) * STAGE_B;
        if (c < NK - 1) asm volatile("cp.async.wait_group 1;" ::: "memory");
        else            asm volatile("cp.async.wait_group 0;" ::: "memory");
        __syncthreads();

        #pragma unroll
        for (int s = 0; s < 4; s++) {               // 4 x k16 per k-tile
            uint32_t ah[4][4], bh[4][2];
            #pragma unroll
            for (int i = 0; i < 4; i++) {
                int row = a_row + i * 16;
                LDSM_X4(ah[i], st + OFF_A + swz(row, s * 2 + a_jlo));
            }
            #pragma unroll
            for (int jj = 0; jj < 2; jj++) {
                int row = b_rb + jj * 16;
                uint32_t r4[4];
                LDSM_X4(r4, st + OFF_B + swz(row, s * 2 + b_jlo));
                bh[jj*2][0] = r4[0]; bh[jj*2][1] = r4[1];
                bh[jj*2+1][0] = r4[2]; bh[jj*2+1][1] = r4[3];
            }
            #pragma unroll
            for (int i = 0; i < 4; i++)
                #pragma unroll
                for (int j = 0; j < 4; j++)
                    mma_fp16(acc[i][j], ah[i], bh[j]);
        }
        __syncthreads();
        if (c + 2 < NK)
            load_stage(sb + (c & 1) * STAGE_B, cbase, wrow, (c + 2) * KC, tid);
    }

    // ---- Epilogue: scatter rows back by atom id, add bias. ----
    const int g  = lane >> 2;
    const int t4 = lane & 3;
    float2 bb[4];
    #pragma unroll
    for (int j = 0; j < 4; j++)
        bb[j] = *reinterpret_cast<const float2*>(
                    bias + d * CQ + n0 + wn + j * 8 + t4 * 2);

    #pragma unroll
    for (int i = 0; i < 4; i++) {
        const int r0 = cbase + wm + i * 16 + g;
        const int a0 = g_rowatom[r0];
        const int a1 = g_rowatom[r0 + 8];
        #pragma unroll
        for (int j = 0; j < 4; j++) {
            const int col = n0 + wn + j * 8 + t4 * 2;
            if (a0 >= 0) {
                float2 v = make_float2(acc[i][j][0] + bb[j].x, acc[i][j][1] + bb[j].y);
                *reinterpret_cast<float2*>(out + (size_t)a0 * CQ + col) = v;
            }
            if (a1 >= 0) {
                float2 v = make_float2(acc[i][j][2] + bb[j].x, acc[i][j][3] + bb[j].y);
                *reinterpret_cast<float2*>(out + (size_t)a1 * CQ + col) = v;
            }
        }
    }
}

// ---------------------------------------------------------------------------
// Launch
// ---------------------------------------------------------------------------
extern "C" void kernel_launch(void* const* d_in, const int* in_sizes, int n_in,
                              void* d_out, int out_size)
{
    const float* atoms = (const float*)d_in[0];   // [B, A, F] fp32
    const int*   bonds = (const int*)  d_in[1];   // [B, A, D] int32
    const float* W     = (const float*)d_in[2];   // [D, F, C] fp32
    const float* bias  = (const float*)d_in[3];   // [D, C]    fp32
    float*       out   = (float*)d_out;           // [B, A, C] fp32

    cudaFuncSetAttribute(gemm_mma_kernel,
                         cudaFuncAttributeMaxDynamicSharedMemorySize, DYN_SMEM);

    wsplit_kernel<<<dim3(FQ / 32, CQ / 32, DQ), dim3(32, 8)>>>(W);   // also resets counters
    bucket_kernel<<<BA / 256, 256>>>(bonds);                         // last block scans
    gather_kernel<<<BA, 128>>>(atoms, bonds);
    gemm_mma_kernel<<<dim3(BA / MT, CQ / NT, DQ), 256, DYN_SMEM>>>(bias, out);
}